// round 1
// baseline (speedup 1.0000x reference)
#include <cuda_runtime.h>
#include <math.h>

#define Bsz 2
#define Ssz 2048
#define Dsz 1024
#define Hsz 16
#define DHsz 64
#define Msz (Bsz * Ssz)          // 4096 rows
#define CHUNK (4096ull * 1024ull)

// Scratch: Q1,K1,V1,Q2,K2,V2,O1,O2,A1,A2  -> 10 chunks of 16MB (BSS, no alloc)
__device__ float g_scratch[10ull * CHUNK];

// ---------------------------------------------------------------------------
// SGEMM: C[M,N] = A[M,K] @ B[K,N] + bias[N], fp32, 128x128 block, 8x8/thread
// ---------------------------------------------------------------------------
__global__ __launch_bounds__(256)
void sgemm_bias(const float* __restrict__ A, const float* __restrict__ B,
                const float* __restrict__ bias, float* __restrict__ C,
                int M, int N, int K)
{
    __shared__ __align__(16) float As[8][128];
    __shared__ __align__(16) float Bs[8][128];

    const int tid = threadIdx.x;
    const int bx = blockIdx.x, by = blockIdx.y;
    const int ty = tid >> 4, tx = tid & 15;

    float acc[8][8];
#pragma unroll
    for (int i = 0; i < 8; i++)
#pragma unroll
        for (int j = 0; j < 8; j++) acc[i][j] = 0.f;

    const int aRow = tid >> 1;           // 0..127
    const int aCol = (tid & 1) * 4;      // 0 or 4
    const int bRow = tid >> 5;           // 0..7
    const int bCol = (tid & 31) * 4;     // 0..124

    const float* Aptr = A + (size_t)(by * 128 + aRow) * K + aCol;
    const float* Bptr = B + (size_t)bRow * N + bx * 128 + bCol;

    for (int kt = 0; kt < K; kt += 8) {
        float4 av = *(const float4*)(Aptr + kt);
        As[aCol + 0][aRow] = av.x;
        As[aCol + 1][aRow] = av.y;
        As[aCol + 2][aRow] = av.z;
        As[aCol + 3][aRow] = av.w;
        *(float4*)&Bs[bRow][bCol] = *(const float4*)(Bptr + (size_t)kt * N);
        __syncthreads();
#pragma unroll
        for (int k = 0; k < 8; k++) {
            float a[8], b[8];
            *(float4*)&a[0] = *(float4*)&As[k][ty * 8];
            *(float4*)&a[4] = *(float4*)&As[k][ty * 8 + 4];
            *(float4*)&b[0] = *(float4*)&Bs[k][tx * 8];
            *(float4*)&b[4] = *(float4*)&Bs[k][tx * 8 + 4];
#pragma unroll
            for (int i = 0; i < 8; i++)
#pragma unroll
                for (int j = 0; j < 8; j++)
                    acc[i][j] = fmaf(a[i], b[j], acc[i][j]);
        }
        __syncthreads();
    }

    const float* brow = bias + bx * 128 + tx * 8;
    float bv[8];
#pragma unroll
    for (int j = 0; j < 8; j++) bv[j] = brow[j];

#pragma unroll
    for (int i = 0; i < 8; i++) {
        int m = by * 128 + ty * 8 + i;
        float* Crow = C + (size_t)m * N + bx * 128 + tx * 8;
        float4 r0, r1;
        r0.x = acc[i][0] + bv[0]; r0.y = acc[i][1] + bv[1];
        r0.z = acc[i][2] + bv[2]; r0.w = acc[i][3] + bv[3];
        r1.x = acc[i][4] + bv[4]; r1.y = acc[i][5] + bv[5];
        r1.z = acc[i][6] + bv[6]; r1.w = acc[i][7] + bv[7];
        *(float4*)(Crow + 0) = r0;
        *(float4*)(Crow + 4) = r1;
    }
}

// ---------------------------------------------------------------------------
// Flash attention (fp32, non-causal). Layouts: Q,K,V,O = [B,S,H,DH] row-major.
// Block = 128 threads, each thread owns one query row (q,o in registers).
// Grid = (S/128, B*H).
// ---------------------------------------------------------------------------
__global__ __launch_bounds__(128)
void flash_attn(const float* __restrict__ Q, const float* __restrict__ K,
                const float* __restrict__ V, float* __restrict__ O)
{
    constexpr int BN = 32;
    __shared__ __align__(16) float Ks[BN][64];
    __shared__ __align__(16) float Vs[BN][64];
    __shared__ float Ss[128][33];   // padded: conflict-free per-thread score rows

    const int tid = threadIdx.x;
    const int bh = blockIdx.y;
    const int b = bh >> 4, h = bh & 15;
    const int qrow = blockIdx.x * 128 + tid;
    const float scale = 0.125f;     // 1/sqrt(64)

    const float* Qp = Q + ((size_t)(b * Ssz + qrow) * Dsz + h * DHsz);
    float q[64], o[64];
#pragma unroll
    for (int i = 0; i < 16; i++) {
        float4 t = *(const float4*)(Qp + i * 4);
        q[i * 4 + 0] = t.x * scale;
        q[i * 4 + 1] = t.y * scale;
        q[i * 4 + 2] = t.z * scale;
        q[i * 4 + 3] = t.w * scale;
    }
#pragma unroll
    for (int i = 0; i < 64; i++) o[i] = 0.f;

    float m = -1e30f, l = 0.f;

    for (int j0 = 0; j0 < Ssz; j0 += BN) {
        // cooperative K/V tile load (coalesced float4)
        for (int i = tid; i < BN * 16; i += 128) {
            int r = i >> 4, c = (i & 15) << 2;
            size_t g = (size_t)(b * Ssz + j0 + r) * Dsz + h * DHsz + c;
            *(float4*)&Ks[r][c] = *(const float4*)(K + g);
            *(float4*)&Vs[r][c] = *(const float4*)(V + g);
        }
        __syncthreads();

        // scores for this tile (Ks reads are warp-uniform -> smem broadcast)
        float tmax = -1e30f;
        for (int j = 0; j < BN; j++) {
            float a0 = 0.f, a1 = 0.f, a2 = 0.f, a3 = 0.f;
#pragma unroll
            for (int d4 = 0; d4 < 16; d4++) {
                float4 kv = *(const float4*)&Ks[j][d4 * 4];
                a0 = fmaf(q[d4 * 4 + 0], kv.x, a0);
                a1 = fmaf(q[d4 * 4 + 1], kv.y, a1);
                a2 = fmaf(q[d4 * 4 + 2], kv.z, a2);
                a3 = fmaf(q[d4 * 4 + 3], kv.w, a3);
            }
            float s = (a0 + a1) + (a2 + a3);
            Ss[tid][j] = s;
            tmax = fmaxf(tmax, s);
        }

        float m_new = fmaxf(m, tmax);
        float alpha = __expf(m - m_new);
        l *= alpha;
#pragma unroll
        for (int d = 0; d < 64; d++) o[d] *= alpha;

        for (int j = 0; j < BN; j++) {
            float p = __expf(Ss[tid][j] - m_new);
            l += p;
#pragma unroll
            for (int d4 = 0; d4 < 16; d4++) {
                float4 vv = *(const float4*)&Vs[j][d4 * 4];
                o[d4 * 4 + 0] = fmaf(p, vv.x, o[d4 * 4 + 0]);
                o[d4 * 4 + 1] = fmaf(p, vv.y, o[d4 * 4 + 1]);
                o[d4 * 4 + 2] = fmaf(p, vv.z, o[d4 * 4 + 2]);
                o[d4 * 4 + 3] = fmaf(p, vv.w, o[d4 * 4 + 3]);
            }
        }
        m = m_new;
        __syncthreads();
    }

    float inv = 1.f / l;
    float* Op = O + ((size_t)(b * Ssz + qrow) * Dsz + h * DHsz);
#pragma unroll
    for (int i = 0; i < 16; i++) {
        float4 t;
        t.x = o[i * 4 + 0] * inv;
        t.y = o[i * 4 + 1] * inv;
        t.z = o[i * 4 + 2] * inv;
        t.w = o[i * 4 + 3] * inv;
        *(float4*)(Op + i * 4) = t;
    }
}

// ---------------------------------------------------------------------------
// diff = a1 - lambda * a2 (in place into a1); lambda computed on device.
// layer_idx may arrive as int32 or float32 bits -> disambiguate by magnitude.
// ---------------------------------------------------------------------------
__global__ void diff_lambda(float* __restrict__ a1, const float* __restrict__ a2,
                            const float* __restrict__ lambda_param,
                            const unsigned* __restrict__ layer_idx_bits, int n)
{
    unsigned bits = *layer_idx_bits;
    float lf = (bits < 10000u) ? (float)bits : __uint_as_float(bits);
    float e = __expf(-0.3f * fmaxf(lf - 1.0f, 0.0f));
    float init = 0.8f - 0.6f * e;
    float lam = fminf(fmaxf(init * lambda_param[0], 0.1f), 0.9f);

    int i = blockIdx.x * blockDim.x + threadIdx.x;
    int stride = gridDim.x * blockDim.x;
    for (; i < n; i += stride)
        a1[i] = fmaf(-lam, a2[i], a1[i]);
}

// ---------------------------------------------------------------------------
extern "C" void kernel_launch(void* const* d_in, const int* in_sizes, int n_in,
                              void* d_out, int out_size)
{
    const float*    x            = (const float*)d_in[0];
    const unsigned* layer_idx    = (const unsigned*)d_in[1];
    const float*    lambda_param = (const float*)d_in[2];

    const float *Wq1, *bq1, *Wk1, *bk1, *Wv1, *bv1, *Wo1, *bo1;
    const float *Wq2, *bq2, *Wk2, *bk2, *Wv2, *bv2, *Wo2, *bo2;

    // Disambiguate input ordering:
    //  dict order:      Wq1 Wk1 Wv1 Wo1 bq1 bk1 bv1 bo1 ...  -> in_sizes[4] = 1048576
    //  signature order: Wq1 bq1 Wk1 bk1 Wv1 bv1 Wo1 bo1 ...  -> in_sizes[4] = 1024
    bool sig_order = (in_sizes[4] < 100000);
    if (!sig_order) {
        Wq1 = (const float*)d_in[3];  Wk1 = (const float*)d_in[4];
        Wv1 = (const float*)d_in[5];  Wo1 = (const float*)d_in[6];
        bq1 = (const float*)d_in[7];  bk1 = (const float*)d_in[8];
        bv1 = (const float*)d_in[9];  bo1 = (const float*)d_in[10];
        Wq2 = (const float*)d_in[11]; Wk2 = (const float*)d_in[12];
        Wv2 = (const float*)d_in[13]; Wo2 = (const float*)d_in[14];
        bq2 = (const float*)d_in[15]; bk2 = (const float*)d_in[16];
        bv2 = (const float*)d_in[17]; bo2 = (const float*)d_in[18];
    } else {
        Wq1 = (const float*)d_in[3];  bq1 = (const float*)d_in[4];
        Wk1 = (const float*)d_in[5];  bk1 = (const float*)d_in[6];
        Wv1 = (const float*)d_in[7];  bv1 = (const float*)d_in[8];
        Wo1 = (const float*)d_in[9];  bo1 = (const float*)d_in[10];
        Wq2 = (const float*)d_in[11]; bq2 = (const float*)d_in[12];
        Wk2 = (const float*)d_in[13]; bk2 = (const float*)d_in[14];
        Wv2 = (const float*)d_in[15]; bv2 = (const float*)d_in[16];
        Wo2 = (const float*)d_in[17]; bo2 = (const float*)d_in[18];
    }
    const float* Wp = (const float*)d_in[19];
    const float* bp = (const float*)d_in[20];

    float* scratch = nullptr;
    cudaGetSymbolAddress((void**)&scratch, g_scratch);
    float* Q1 = scratch + 0 * CHUNK;
    float* K1 = scratch + 1 * CHUNK;
    float* V1 = scratch + 2 * CHUNK;
    float* Q2 = scratch + 3 * CHUNK;
    float* K2 = scratch + 4 * CHUNK;
    float* V2 = scratch + 5 * CHUNK;
    float* O1 = scratch + 6 * CHUNK;
    float* O2 = scratch + 7 * CHUNK;
    float* A1 = scratch + 8 * CHUNK;
    float* A2 = scratch + 9 * CHUNK;

    dim3 gg(Dsz / 128, Msz / 128);   // (8, 32)
    dim3 gb(256);

    // QKV projections (weights are [D, H*DH] row-major when flattened)
    sgemm_bias<<<gg, gb>>>(x, Wq1, bq1, Q1, Msz, Dsz, Dsz);
    sgemm_bias<<<gg, gb>>>(x, Wk1, bk1, K1, Msz, Dsz, Dsz);
    sgemm_bias<<<gg, gb>>>(x, Wv1, bv1, V1, Msz, Dsz, Dsz);
    sgemm_bias<<<gg, gb>>>(x, Wq2, bq2, Q2, Msz, Dsz, Dsz);
    sgemm_bias<<<gg, gb>>>(x, Wk2, bk2, K2, Msz, Dsz, Dsz);
    sgemm_bias<<<gg, gb>>>(x, Wv2, bv2, V2, Msz, Dsz, Dsz);

    // Attention per branch
    dim3 fg(Ssz / 128, Bsz * Hsz);   // (16, 32)
    flash_attn<<<fg, 128>>>(Q1, K1, V1, O1);
    flash_attn<<<fg, 128>>>(Q2, K2, V2, O2);

    // Output projections (Wo flattened [H*DH, D])
    sgemm_bias<<<gg, gb>>>(O1, Wo1, bo1, A1, Msz, Dsz, Dsz);
    sgemm_bias<<<gg, gb>>>(O2, Wo2, bo2, A2, Msz, Dsz, Dsz);

    // diff = a1 - lambda * a2 (in place)
    diff_lambda<<<512, 256>>>(A1, A2, lambda_param, layer_idx, (int)(Msz * (size_t)Dsz));

    // final projection into d_out
    sgemm_bias<<<gg, gb>>>(A1, Wp, bp, (float*)d_out, Msz, Dsz, Dsz);
}

// round 3
// speedup vs baseline: 3.7479x; 3.7479x over previous
#include <cuda_runtime.h>
#include <math.h>
#include <stdint.h>

#define Bsz 2
#define Ssz 2048
#define Dsz 1024
#define Hsz 16
#define DHsz 64
#define Msz (Bsz * Ssz)            // 4096 rows
#define CHUNK (4096ull * 1024ull)  // 16 MB of floats
#define WCH   (1024ull * 1024ull)  // 4 MB weight chunk

// 11 activation chunks + 9 rounded-weight chunks (BSS, no alloc)
__device__ __align__(1024) float g_scratch[11ull * CHUNK + 9ull * WCH];

// ---------------------------------------------------------------------------
// helpers
// ---------------------------------------------------------------------------
__device__ __forceinline__ uint32_t cvta_smem(const void* p) {
    uint32_t a;
    asm("{ .reg .u64 t; cvta.to.shared.u64 t, %1; cvt.u32.u64 %0, t; }"
        : "=r"(a) : "l"(p));
    return a;
}
__device__ __forceinline__ void cp16(uint32_t dst, const void* src) {
    asm volatile("cp.async.cg.shared.global [%0], [%1], 16;" :: "r"(dst), "l"(src));
}
__device__ __forceinline__ void cp_commit() { asm volatile("cp.async.commit_group;"); }
template <int N>
__device__ __forceinline__ void cp_wait() { asm volatile("cp.async.wait_group %0;" :: "n"(N)); }

__device__ __forceinline__ float rna_tf32(float v) {
    uint32_t b;
    asm("cvt.rna.tf32.f32 %0, %1;" : "=r"(b) : "f"(v));
    return __uint_as_float(b);
}
__device__ __forceinline__ uint32_t rna_bits(float v) {
    uint32_t b;
    asm("cvt.rna.tf32.f32 %0, %1;" : "=r"(b) : "f"(v));
    return b;
}

// mma.sync m16n8k8 tf32: D += A(16x8, row) * B(8x8, col)
__device__ __forceinline__ void mma8(float c[4], const uint32_t a[4],
                                     uint32_t b0, uint32_t b1) {
    asm volatile(
        "mma.sync.aligned.m16n8k8.row.col.f32.tf32.tf32.f32 "
        "{%0,%1,%2,%3}, {%4,%5,%6,%7}, {%8,%9}, {%0,%1,%2,%3};"
        : "+f"(c[0]), "+f"(c[1]), "+f"(c[2]), "+f"(c[3])
        : "r"(a[0]), "r"(a[1]), "r"(a[2]), "r"(a[3]), "r"(b0), "r"(b1));
}

// ---------------------------------------------------------------------------
// tf32 mma.sync GEMM: C[M,N] = A[M,K] @ B[K,N] + bias[N]
// A,B pre-rounded tf32. CTA tile 128x128, BK=32, 256 thr (8 warps, 4x2).
// ---------------------------------------------------------------------------
#define ALD 36
#define BLD 136
#define ASZ (128 * ALD)          // 4608 floats
#define BSZ_ (32 * BLD)          // 4352 floats
#define GEMM_SMEM ((2 * ASZ + 2 * BSZ_) * 4)  // 71680 B

template <bool ROUND>
__global__ __launch_bounds__(256)
void gemm_mma(const float* __restrict__ A, const float* __restrict__ B,
              const float* __restrict__ bias, float* __restrict__ C,
              int M, int N, int K)
{
    extern __shared__ float sm[];
    float* As = sm;                // [2][ASZ]
    float* Bs = sm + 2 * ASZ;      // [2][BSZ_]
    const uint32_t sb = cvta_smem(sm);
    const uint32_t sbB = cvta_smem(Bs);

    const int tid = threadIdx.x;
    const int wid = tid >> 5, lane = tid & 31;
    const int g = lane >> 2, t = lane & 3;
    const int wm = wid >> 1, wn = wid & 1;
    const int m0 = blockIdx.y * 128, n0 = blockIdx.x * 128;

    float c[2][8][4] = {};

    auto loadA = [&](int buf, int kt) {
#pragma unroll
        for (int i = 0; i < 4; i++) {
            int idx = tid + i * 256;
            int row = idx >> 3, c4 = (idx & 7) << 2;
            cp16(sb + (uint32_t)(buf * ASZ + row * ALD + c4) * 4u,
                 A + (size_t)(m0 + row) * K + kt * 32 + c4);
        }
    };
    auto loadB = [&](int buf, int kt) {
#pragma unroll
        for (int i = 0; i < 4; i++) {
            int idx = tid + i * 256;
            int row = idx >> 5, c4 = (idx & 31) << 2;
            cp16(sbB + (uint32_t)(buf * BSZ_ + row * BLD + c4) * 4u,
                 B + (size_t)(kt * 32 + row) * N + n0 + c4);
        }
    };

    const int T = K / 32;
    loadA(0, 0); loadB(0, 0); cp_commit();

    for (int kt = 0; kt < T; kt++) {
        const int buf = kt & 1;
        if (kt + 1 < T) { loadA(buf ^ 1, kt + 1); loadB(buf ^ 1, kt + 1); cp_commit(); cp_wait<1>(); }
        else cp_wait<0>();
        __syncthreads();

        const uint32_t* Ab = (const uint32_t*)(As + buf * ASZ);
        const uint32_t* Bb = (const uint32_t*)(Bs + buf * BSZ_);
#pragma unroll
        for (int ks = 0; ks < 4; ks++) {
            uint32_t a[2][4];
#pragma unroll
            for (int mf = 0; mf < 2; mf++) {
                int rb = wm * 32 + mf * 16;
                a[mf][0] = Ab[(rb + g) * ALD + ks * 8 + t];
                a[mf][1] = Ab[(rb + g + 8) * ALD + ks * 8 + t];
                a[mf][2] = Ab[(rb + g) * ALD + ks * 8 + t + 4];
                a[mf][3] = Ab[(rb + g + 8) * ALD + ks * 8 + t + 4];
            }
#pragma unroll
            for (int nf = 0; nf < 8; nf++) {
                uint32_t b0 = Bb[(ks * 8 + t) * BLD + wn * 64 + nf * 8 + g];
                uint32_t b1 = Bb[(ks * 8 + t + 4) * BLD + wn * 64 + nf * 8 + g];
#pragma unroll
                for (int mf = 0; mf < 2; mf++)
                    mma8(c[mf][nf], a[mf], b0, b1);
            }
        }
        __syncthreads();
    }

    const float* brow = bias + n0 + wn * 64;
#pragma unroll
    for (int mf = 0; mf < 2; mf++) {
        int r0 = m0 + wm * 32 + mf * 16 + g;
#pragma unroll
        for (int nf = 0; nf < 8; nf++) {
            int col = wn * 64 + nf * 8 + 2 * t;
            float bv0 = brow[nf * 8 + 2 * t];
            float bv1 = brow[nf * 8 + 2 * t + 1];
            float v00 = c[mf][nf][0] + bv0, v01 = c[mf][nf][1] + bv1;
            float v10 = c[mf][nf][2] + bv0, v11 = c[mf][nf][3] + bv1;
            if (ROUND) {
                v00 = rna_tf32(v00); v01 = rna_tf32(v01);
                v10 = rna_tf32(v10); v11 = rna_tf32(v11);
            }
            float2 lo = { v00, v01 }, hi = { v10, v11 };
            *(float2*)(C + (size_t)r0 * N + n0 + col) = lo;
            *(float2*)(C + (size_t)(r0 + 8) * N + n0 + col) = hi;
        }
    }
}

// ---------------------------------------------------------------------------
// Flash attention with tf32 mma.sync. Q,K,V pre-rounded tf32, [B,S,H,DH].
// CTA: 4 warps, 64 q-rows. KV tile 64, double-buffered cp.async.
// Writes O rounded to tf32.
// ---------------------------------------------------------------------------
#define KLD 68
#define VLD 72
#define PLD 65
#define KSZ (64 * KLD)   // 4352 floats
#define VSZ (64 * VLD)   // 4608 floats
#define PSZ (64 * PLD)   // 4160 floats
#define ATT_SMEM ((2 * KSZ + 2 * VSZ + PSZ) * 4)  // 88320 B

__global__ __launch_bounds__(128)
void flash_mma(const float* __restrict__ Q, const float* __restrict__ K,
               const float* __restrict__ V, float* __restrict__ O)
{
    extern __shared__ float sm[];
    float* Ks = sm;
    float* Vs = sm + 2 * KSZ;
    float* Ps = sm + 2 * KSZ + 2 * VSZ;
    const uint32_t sb = cvta_smem(sm);

    const int tid = threadIdx.x;
    const int w = tid >> 5, lane = tid & 31;
    const int g = lane >> 2, t = lane & 3;
    const int bh = blockIdx.y, b = bh >> 4, h = bh & 15;
    const int q0 = blockIdx.x * 64;

    // Q fragments (scaled by 1/8: exact power of 2, keeps tf32)
    uint32_t qf[8][4];
    {
        const float* Qlo = Q + ((size_t)(b * Ssz + q0 + w * 16 + g) * Dsz + h * 64);
        const float* Qhi = Qlo + 8 * (size_t)Dsz;
#pragma unroll
        for (int kf = 0; kf < 8; kf++) {
            qf[kf][0] = __float_as_uint(Qlo[kf * 8 + t] * 0.125f);
            qf[kf][1] = __float_as_uint(Qhi[kf * 8 + t] * 0.125f);
            qf[kf][2] = __float_as_uint(Qlo[kf * 8 + t + 4] * 0.125f);
            qf[kf][3] = __float_as_uint(Qhi[kf * 8 + t + 4] * 0.125f);
        }
    }

    float o[8][4] = {};
    float m0f = -1e30f, m1f = -1e30f, l0 = 0.f, l1 = 0.f;

    auto loadKV = [&](int buf, int tile) {
#pragma unroll
        for (int i = 0; i < 8; i++) {
            int idx = tid + i * 128;
            int row = idx >> 4, c4 = (idx & 15) << 2;
            size_t gsrc = (size_t)(b * Ssz + tile * 64 + row) * Dsz + h * 64 + c4;
            cp16(sb + (uint32_t)(buf * KSZ + row * KLD + c4) * 4u, K + gsrc);
            cp16(sb + (uint32_t)(2 * KSZ + buf * VSZ + row * VLD + c4) * 4u, V + gsrc);
        }
    };

    const int NT = Ssz / 64;   // 32
    loadKV(0, 0); cp_commit();

    for (int tile = 0; tile < NT; tile++) {
        const int buf = tile & 1;
        if (tile + 1 < NT) { loadKV(buf ^ 1, tile + 1); cp_commit(); cp_wait<1>(); }
        else cp_wait<0>();
        __syncthreads();

        const uint32_t* Kb = (const uint32_t*)(Ks + buf * KSZ);
        const uint32_t* Vb = (const uint32_t*)(Vs + buf * VSZ);

        // S = Q * K^T  (16 x 64 per warp)
        float s[8][4] = {};
#pragma unroll
        for (int kf = 0; kf < 8; kf++) {
#pragma unroll
            for (int nf = 0; nf < 8; nf++) {
                uint32_t b0 = Kb[(nf * 8 + g) * KLD + kf * 8 + t];
                uint32_t b1 = Kb[(nf * 8 + g) * KLD + kf * 8 + t + 4];
                mma8(s[nf], qf[kf], b0, b1);
            }
        }

        // online softmax (rows g and g+8; quads share a row)
        float tmax0 = -1e30f, tmax1 = -1e30f;
#pragma unroll
        for (int nf = 0; nf < 8; nf++) {
            tmax0 = fmaxf(tmax0, fmaxf(s[nf][0], s[nf][1]));
            tmax1 = fmaxf(tmax1, fmaxf(s[nf][2], s[nf][3]));
        }
        tmax0 = fmaxf(tmax0, __shfl_xor_sync(0xffffffffu, tmax0, 1));
        tmax0 = fmaxf(tmax0, __shfl_xor_sync(0xffffffffu, tmax0, 2));
        tmax1 = fmaxf(tmax1, __shfl_xor_sync(0xffffffffu, tmax1, 1));
        tmax1 = fmaxf(tmax1, __shfl_xor_sync(0xffffffffu, tmax1, 2));

        float mn0 = fmaxf(m0f, tmax0), mn1 = fmaxf(m1f, tmax1);
        float al0 = __expf(m0f - mn0), al1 = __expf(m1f - mn1);

        uint32_t* Pu = (uint32_t*)Ps;
        const int prow0 = (w * 16 + g) * PLD;
        const int prow1 = (w * 16 + g + 8) * PLD;
        float rs0 = 0.f, rs1 = 0.f;
#pragma unroll
        for (int nf = 0; nf < 8; nf++) {
            float p0 = __expf(s[nf][0] - mn0);
            float p1 = __expf(s[nf][1] - mn0);
            float p2 = __expf(s[nf][2] - mn1);
            float p3 = __expf(s[nf][3] - mn1);
            uint32_t r0 = rna_bits(p0), r1 = rna_bits(p1);
            uint32_t r2 = rna_bits(p2), r3 = rna_bits(p3);
            rs0 += __uint_as_float(r0) + __uint_as_float(r1);
            rs1 += __uint_as_float(r2) + __uint_as_float(r3);
            Pu[prow0 + nf * 8 + 2 * t]     = r0;
            Pu[prow0 + nf * 8 + 2 * t + 1] = r1;
            Pu[prow1 + nf * 8 + 2 * t]     = r2;
            Pu[prow1 + nf * 8 + 2 * t + 1] = r3;
        }
        rs0 += __shfl_xor_sync(0xffffffffu, rs0, 1);
        rs0 += __shfl_xor_sync(0xffffffffu, rs0, 2);
        rs1 += __shfl_xor_sync(0xffffffffu, rs1, 1);
        rs1 += __shfl_xor_sync(0xffffffffu, rs1, 2);
        l0 = l0 * al0 + rs0;
        l1 = l1 * al1 + rs1;
        m0f = mn0; m1f = mn1;

#pragma unroll
        for (int nf = 0; nf < 8; nf++) {
            o[nf][0] *= al0; o[nf][1] *= al0;
            o[nf][2] *= al1; o[nf][3] *= al1;
        }
        __syncwarp();

        // O += P * V
        const uint32_t* Pr = (const uint32_t*)Ps;
#pragma unroll
        for (int kf = 0; kf < 8; kf++) {
            uint32_t a[4];
            a[0] = Pr[prow0 + kf * 8 + t];
            a[1] = Pr[prow1 + kf * 8 + t];
            a[2] = Pr[prow0 + kf * 8 + t + 4];
            a[3] = Pr[prow1 + kf * 8 + t + 4];
#pragma unroll
            for (int nf = 0; nf < 8; nf++) {
                uint32_t b0 = Vb[(kf * 8 + t) * VLD + nf * 8 + g];
                uint32_t b1 = Vb[(kf * 8 + t + 4) * VLD + nf * 8 + g];
                mma8(o[nf], a, b0, b1);
            }
        }
        __syncthreads();
    }

    const float inv0 = 1.f / l0, inv1 = 1.f / l1;
    float* Orow = O + ((size_t)(b * Ssz + q0 + w * 16 + g) * Dsz + h * 64);
#pragma unroll
    for (int nf = 0; nf < 8; nf++) {
        int col = nf * 8 + 2 * t;
        float2 lo = { rna_tf32(o[nf][0] * inv0), rna_tf32(o[nf][1] * inv0) };
        float2 hi = { rna_tf32(o[nf][2] * inv1), rna_tf32(o[nf][3] * inv1) };
        *(float2*)(Orow + col) = lo;
        *(float2*)(Orow + 8 * (size_t)Dsz + col) = hi;
    }
}

// ---------------------------------------------------------------------------
// round-to-tf32 elementwise copy
// ---------------------------------------------------------------------------
__global__ void round_tf32_copy(const float4* __restrict__ in, float4* __restrict__ out, int n4)
{
    int i = blockIdx.x * blockDim.x + threadIdx.x;
    int st = gridDim.x * blockDim.x;
    for (; i < n4; i += st) {
        float4 v = in[i];
        v.x = rna_tf32(v.x); v.y = rna_tf32(v.y);
        v.z = rna_tf32(v.z); v.w = rna_tf32(v.w);
        out[i] = v;
    }
}

// ---------------------------------------------------------------------------
// diff = rna_tf32(a1 - lambda * a2), in place into a1
// ---------------------------------------------------------------------------
__global__ void diff_lambda(float* __restrict__ a1, const float* __restrict__ a2,
                            const float* __restrict__ lambda_param,
                            const unsigned* __restrict__ layer_idx_bits, int n)
{
    unsigned bits = *layer_idx_bits;
    float lf = (bits < 10000u) ? (float)bits : __uint_as_float(bits);
    float e = __expf(-0.3f * fmaxf(lf - 1.0f, 0.0f));
    float init = 0.8f - 0.6f * e;
    float lam = fminf(fmaxf(init * lambda_param[0], 0.1f), 0.9f);

    int i = blockIdx.x * blockDim.x + threadIdx.x;
    int stride = gridDim.x * blockDim.x;
    for (; i < n; i += stride)
        a1[i] = rna_tf32(fmaf(-lam, a2[i], a1[i]));
}

// ---------------------------------------------------------------------------
extern "C" void kernel_launch(void* const* d_in, const int* in_sizes, int n_in,
                              void* d_out, int out_size)
{
    const float*    x            = (const float*)d_in[0];
    const unsigned* layer_idx    = (const unsigned*)d_in[1];
    const float*    lambda_param = (const float*)d_in[2];

    const float *Wq1, *bq1, *Wk1, *bk1, *Wv1, *bv1, *Wo1, *bo1;
    const float *Wq2, *bq2, *Wk2, *bk2, *Wv2, *bv2, *Wo2, *bo2;

    bool sig_order = (in_sizes[4] < 100000);
    if (!sig_order) {
        Wq1 = (const float*)d_in[3];  Wk1 = (const float*)d_in[4];
        Wv1 = (const float*)d_in[5];  Wo1 = (const float*)d_in[6];
        bq1 = (const float*)d_in[7];  bk1 = (const float*)d_in[8];
        bv1 = (const float*)d_in[9];  bo1 = (const float*)d_in[10];
        Wq2 = (const float*)d_in[11]; Wk2 = (const float*)d_in[12];
        Wv2 = (const float*)d_in[13]; Wo2 = (const float*)d_in[14];
        bq2 = (const float*)d_in[15]; bk2 = (const float*)d_in[16];
        bv2 = (const float*)d_in[17]; bo2 = (const float*)d_in[18];
    } else {
        Wq1 = (const float*)d_in[3];  bq1 = (const float*)d_in[4];
        Wk1 = (const float*)d_in[5];  bk1 = (const float*)d_in[6];
        Wv1 = (const float*)d_in[7];  bv1 = (const float*)d_in[8];
        Wo1 = (const float*)d_in[9];  bo1 = (const float*)d_in[10];
        Wq2 = (const float*)d_in[11]; bq2 = (const float*)d_in[12];
        Wk2 = (const float*)d_in[13]; bk2 = (const float*)d_in[14];
        Wv2 = (const float*)d_in[15]; bv2 = (const float*)d_in[16];
        Wo2 = (const float*)d_in[17]; bo2 = (const float*)d_in[18];
    }
    const float* Wp = (const float*)d_in[19];
    const float* bp = (const float*)d_in[20];

    float* scratch = nullptr;
    cudaGetSymbolAddress((void**)&scratch, g_scratch);
    float* Q1 = scratch + 0 * CHUNK;
    float* K1 = scratch + 1 * CHUNK;
    float* V1 = scratch + 2 * CHUNK;
    float* Q2 = scratch + 3 * CHUNK;
    float* K2 = scratch + 4 * CHUNK;
    float* V2 = scratch + 5 * CHUNK;
    float* O1 = scratch + 6 * CHUNK;
    float* O2 = scratch + 7 * CHUNK;
    float* T1 = scratch + 8 * CHUNK;
    float* T2 = scratch + 9 * CHUNK;
    float* XR = scratch + 10 * CHUNK;
    float* WR = scratch + 11 * CHUNK;   // 9 x [1024,1024] rounded weights

    cudaFuncSetAttribute(gemm_mma<true>,  cudaFuncAttributeMaxDynamicSharedMemorySize, GEMM_SMEM);
    cudaFuncSetAttribute(gemm_mma<false>, cudaFuncAttributeMaxDynamicSharedMemorySize, GEMM_SMEM);
    cudaFuncSetAttribute(flash_mma,       cudaFuncAttributeMaxDynamicSharedMemorySize, ATT_SMEM);

    // round x and the 9 weights to tf32 (RN)
    round_tf32_copy<<<512, 256>>>((const float4*)x, (float4*)XR, (int)(Msz * (size_t)Dsz / 4));
    const float* Ws[9] = { Wq1, Wk1, Wv1, Wq2, Wk2, Wv2, Wo1, Wo2, Wp };
    for (int i = 0; i < 9; i++)
        round_tf32_copy<<<256, 256>>>((const float4*)Ws[i], (float4*)(WR + (size_t)i * WCH),
                                      (int)(WCH / 4));

    dim3 gg(Dsz / 128, Msz / 128);   // (8, 32)

    // QKV projections (outputs rounded for attention)
    gemm_mma<true><<<gg, 256, GEMM_SMEM>>>(XR, WR + 0 * WCH, bq1, Q1, Msz, Dsz, Dsz);
    gemm_mma<true><<<gg, 256, GEMM_SMEM>>>(XR, WR + 1 * WCH, bk1, K1, Msz, Dsz, Dsz);
    gemm_mma<true><<<gg, 256, GEMM_SMEM>>>(XR, WR + 2 * WCH, bv1, V1, Msz, Dsz, Dsz);
    gemm_mma<true><<<gg, 256, GEMM_SMEM>>>(XR, WR + 3 * WCH, bq2, Q2, Msz, Dsz, Dsz);
    gemm_mma<true><<<gg, 256, GEMM_SMEM>>>(XR, WR + 4 * WCH, bk2, K2, Msz, Dsz, Dsz);
    gemm_mma<true><<<gg, 256, GEMM_SMEM>>>(XR, WR + 5 * WCH, bv2, V2, Msz, Dsz, Dsz);

    // attention (outputs rounded)
    dim3 fg(Ssz / 64, Bsz * Hsz);    // (32, 32)
    flash_mma<<<fg, 128, ATT_SMEM>>>(Q1, K1, V1, O1);
    flash_mma<<<fg, 128, ATT_SMEM>>>(Q2, K2, V2, O2);

    // output projections
    gemm_mma<false><<<gg, 256, GEMM_SMEM>>>(O1, WR + 6 * WCH, bo1, T1, Msz, Dsz, Dsz);
    gemm_mma<false><<<gg, 256, GEMM_SMEM>>>(O2, WR + 7 * WCH, bo2, T2, Msz, Dsz, Dsz);

    // diff (writes rounded result in place into T1)
    diff_lambda<<<512, 256>>>(T1, T2, lambda_param, layer_idx, (int)(Msz * (size_t)Dsz));

    // final projection into d_out
    gemm_mma<false><<<gg, 256, GEMM_SMEM>>>(T1, WR + 8 * WCH, bp, (float*)d_out, Msz, Dsz, Dsz);
}

// round 4
// speedup vs baseline: 4.7681x; 1.2722x over previous
#include <cuda_runtime.h>
#include <math.h>
#include <stdint.h>

#define Bsz 2
#define Ssz 2048
#define Dsz 1024
#define Hsz 16
#define Msz (Bsz * Ssz)            // 4096 rows
#define CHUNK (4096ull * 1024ull)  // 4M floats
#define WCH   (1024ull * 1024ull)  // 1M floats

// XR(1) + QKV(6) + O(2) + T(2) + D(1) chunks + WQKV(6)+WWO(2)+WP(1) WCH + biases
__device__ __align__(1024) float g_scratch[12ull * CHUNK + 9ull * WCH + 16384ull];

// ---------------------------------------------------------------------------
// helpers
// ---------------------------------------------------------------------------
__device__ __forceinline__ uint32_t cvta_smem(const void* p) {
    uint32_t a;
    asm("{ .reg .u64 t; cvta.to.shared.u64 t, %1; cvt.u32.u64 %0, t; }"
        : "=r"(a) : "l"(p));
    return a;
}
__device__ __forceinline__ void cp16(uint32_t dst, const void* src) {
    asm volatile("cp.async.cg.shared.global [%0], [%1], 16;" :: "r"(dst), "l"(src));
}
__device__ __forceinline__ void cp_commit() { asm volatile("cp.async.commit_group;"); }
template <int N>
__device__ __forceinline__ void cp_wait() { asm volatile("cp.async.wait_group %0;" :: "n"(N)); }

__device__ __forceinline__ float rna_tf32(float v) {
    uint32_t b;
    asm("cvt.rna.tf32.f32 %0, %1;" : "=r"(b) : "f"(v));
    return __uint_as_float(b);
}
__device__ __forceinline__ uint32_t rna_bits(float v) {
    uint32_t b;
    asm("cvt.rna.tf32.f32 %0, %1;" : "=r"(b) : "f"(v));
    return b;
}

// mma.sync m16n8k8 tf32: D += A(16x8, row) * B(8x8, col)
__device__ __forceinline__ void mma8(float c[4], const uint32_t a[4],
                                     uint32_t b0, uint32_t b1) {
    asm volatile(
        "mma.sync.aligned.m16n8k8.row.col.f32.tf32.tf32.f32 "
        "{%0,%1,%2,%3}, {%4,%5,%6,%7}, {%8,%9}, {%0,%1,%2,%3};"
        : "+f"(c[0]), "+f"(c[1]), "+f"(c[2]), "+f"(c[3])
        : "r"(a[0]), "r"(a[1]), "r"(a[2]), "r"(a[3]), "r"(b0), "r"(b1));
}

// ---------------------------------------------------------------------------
// tf32 mma.sync GEMM: C[M,N] = A[M,K=1024] @ B[1024,N] + bias[N]
// CTA tile 128x256, BK=32, 256 thr (8 warps, warp tile 64x64).
// BDIAG: block-diagonal A column offset (for fused Wo1/Wo2).
// ---------------------------------------------------------------------------
#define ALD 36
#define BLD 264
#define ASZ (128 * ALD)           // 4608 floats
#define BSZ_ (32 * BLD)           // 8448 floats
#define GEMM_SMEM ((2 * ASZ + 2 * BSZ_) * 4)   // 104448 B

template <bool ROUND, bool BDIAG>
__global__ __launch_bounds__(256, 1)
void gemm_mma(const float* __restrict__ A, const float* __restrict__ B,
              const float* __restrict__ bias, float* __restrict__ C,
              int N, int lda)
{
    extern __shared__ float sm[];
    float* As = sm;                 // [2][128][ALD]
    float* Bs = sm + 2 * ASZ;       // [2][32][BLD]
    const uint32_t sbA = cvta_smem(As);
    const uint32_t sbB = cvta_smem(Bs);

    const int tid = threadIdx.x;
    const int wid = tid >> 5, lane = tid & 31;
    const int g = lane >> 2, t = lane & 3;
    const int wm = wid >> 2, wn = wid & 3;       // 2 x 4 warp grid
    const int m0 = blockIdx.y * 128, n0 = blockIdx.x * 256;
    const int aoff = BDIAG ? (n0 & ~1023) : 0;

    float c[4][8][4] = {};

    auto loadA = [&](int buf, int kt) {
#pragma unroll
        for (int i = 0; i < 4; i++) {
            int idx = tid + i * 256;
            int row = idx >> 3, c4 = (idx & 7) << 2;
            cp16(sbA + (uint32_t)(buf * ASZ + row * ALD + c4) * 4u,
                 A + (size_t)(m0 + row) * lda + aoff + kt * 32 + c4);
        }
    };
    auto loadB = [&](int buf, int kt) {
#pragma unroll
        for (int i = 0; i < 8; i++) {
            int idx = tid + i * 256;
            int row = idx >> 6, c4 = (idx & 63) << 2;
            cp16(sbB + (uint32_t)(buf * BSZ_ + row * BLD + c4) * 4u,
                 B + (size_t)(kt * 32 + row) * N + n0 + c4);
        }
    };

    const int T = 1024 / 32;
    loadA(0, 0); loadB(0, 0); cp_commit();

    for (int kt = 0; kt < T; kt++) {
        const int buf = kt & 1;
        if (kt + 1 < T) { loadA(buf ^ 1, kt + 1); loadB(buf ^ 1, kt + 1); cp_commit(); cp_wait<1>(); }
        else cp_wait<0>();
        __syncthreads();

        const uint32_t* Ab = (const uint32_t*)(As + buf * ASZ);
        const uint32_t* Bb = (const uint32_t*)(Bs + buf * BSZ_);
#pragma unroll
        for (int ks = 0; ks < 4; ks++) {
            uint32_t a[4][4];
#pragma unroll
            for (int mf = 0; mf < 4; mf++) {
                int rb = wm * 64 + mf * 16;
                a[mf][0] = Ab[(rb + g) * ALD + ks * 8 + t];
                a[mf][1] = Ab[(rb + g + 8) * ALD + ks * 8 + t];
                a[mf][2] = Ab[(rb + g) * ALD + ks * 8 + t + 4];
                a[mf][3] = Ab[(rb + g + 8) * ALD + ks * 8 + t + 4];
            }
#pragma unroll
            for (int nf = 0; nf < 8; nf++) {
                uint32_t b0 = Bb[(ks * 8 + t) * BLD + wn * 64 + nf * 8 + g];
                uint32_t b1 = Bb[(ks * 8 + t + 4) * BLD + wn * 64 + nf * 8 + g];
#pragma unroll
                for (int mf = 0; mf < 4; mf++)
                    mma8(c[mf][nf], a[mf], b0, b1);
            }
        }
        __syncthreads();
    }

#pragma unroll
    for (int mf = 0; mf < 4; mf++) {
        int r0 = m0 + wm * 64 + mf * 16 + g;
#pragma unroll
        for (int nf = 0; nf < 8; nf++) {
            int col = n0 + wn * 64 + nf * 8 + 2 * t;
            float bv0 = bias[col], bv1 = bias[col + 1];
            float v00 = c[mf][nf][0] + bv0, v01 = c[mf][nf][1] + bv1;
            float v10 = c[mf][nf][2] + bv0, v11 = c[mf][nf][3] + bv1;
            if (ROUND) {
                v00 = rna_tf32(v00); v01 = rna_tf32(v01);
                v10 = rna_tf32(v10); v11 = rna_tf32(v11);
            }
            float2 lo = { v00, v01 }, hi = { v10, v11 };
            *(float2*)(C + (size_t)r0 * N + col) = lo;
            *(float2*)(C + (size_t)(r0 + 8) * N + col) = hi;
        }
    }
}

// ---------------------------------------------------------------------------
// Flash attention, tf32 mma.sync, both branches via blockIdx.z.
// QKV: [M, 6144] fused (Q1 K1 V1 Q2 K2 V2 blocks of 1024 cols, [H,DH] inside).
// O:   [M, 2048] (branch z at col z*1024).
// CTA: 8 warps, 256 q-rows (32/warp, mf=2). KV tile 64, double-buffered.
// ---------------------------------------------------------------------------
#define KLD 68
#define VLD 72
#define PLD 68
#define KSZ (64 * KLD)
#define VSZ (64 * VLD)
#define PSZ (256 * PLD)
#define ATT_SMEM ((2 * KSZ + 2 * VSZ + PSZ) * 4)   // 141312 B

__global__ __launch_bounds__(256, 1)
void flash_mma(const float* __restrict__ QKV, float* __restrict__ O)
{
    extern __shared__ float sm[];
    float* Ks = sm;
    float* Vs = sm + 2 * KSZ;
    float* Ps = sm + 2 * KSZ + 2 * VSZ;
    const uint32_t sbK = cvta_smem(Ks);
    const uint32_t sbV = cvta_smem(Vs);

    const int tid = threadIdx.x;
    const int w = tid >> 5, lane = tid & 31;
    const int g = lane >> 2, t = lane & 3;
    const int b = blockIdx.y >> 4, h = blockIdx.y & 15, z = blockIdx.z;
    const int q0 = blockIdx.x * 256;
    const size_t ld = 6144;

    const float* Qb = QKV + (size_t)b * Ssz * ld + (size_t)z * 3072 + h * 64;
    const float* Kg = Qb + 1024;
    const float* Vg = Qb + 2048;

    // Q fragments, scaled by 1/8 (exact pow2, stays tf32)
    uint32_t qf[2][8][4];
#pragma unroll
    for (int mf = 0; mf < 2; mf++) {
        const float* r0p = Qb + (size_t)(q0 + w * 32 + mf * 16 + g) * ld;
        const float* r1p = r0p + 8 * ld;
#pragma unroll
        for (int kf = 0; kf < 8; kf++) {
            qf[mf][kf][0] = __float_as_uint(r0p[kf * 8 + t] * 0.125f);
            qf[mf][kf][1] = __float_as_uint(r1p[kf * 8 + t] * 0.125f);
            qf[mf][kf][2] = __float_as_uint(r0p[kf * 8 + t + 4] * 0.125f);
            qf[mf][kf][3] = __float_as_uint(r1p[kf * 8 + t + 4] * 0.125f);
        }
    }

    float o[2][8][4] = {};
    float mm[2][2] = { {-1e30f, -1e30f}, {-1e30f, -1e30f} };
    float ll[2][2] = {};

    auto loadKV = [&](int buf, int tile) {
#pragma unroll
        for (int i = 0; i < 4; i++) {
            int idx = tid + i * 256;
            int row = idx >> 4, c4 = (idx & 15) << 2;
            size_t src = (size_t)(tile * 64 + row) * ld + c4;
            cp16(sbK + (uint32_t)(buf * KSZ + row * KLD + c4) * 4u, Kg + src);
            cp16(sbV + (uint32_t)(buf * VSZ + row * VLD + c4) * 4u, Vg + src);
        }
    };

    const int NT = Ssz / 64;   // 32
    loadKV(0, 0); cp_commit();

    const int pr00 = (w * 32 + g) * PLD;
    const int pr01 = pr00 + 8 * PLD;
    const int pr10 = pr00 + 16 * PLD;
    const int pr11 = pr00 + 24 * PLD;
    uint32_t* Pu = (uint32_t*)Ps;

    for (int tile = 0; tile < NT; tile++) {
        const int buf = tile & 1;
        if (tile + 1 < NT) { loadKV(buf ^ 1, tile + 1); cp_commit(); cp_wait<1>(); }
        else cp_wait<0>();
        __syncthreads();

        const uint32_t* Kb = (const uint32_t*)(Ks + buf * KSZ);
        const uint32_t* Vb = (const uint32_t*)(Vs + buf * VSZ);

        // S = Q * K^T  (32 x 64 per warp)
        float s[2][8][4] = {};
#pragma unroll
        for (int kf = 0; kf < 8; kf++) {
#pragma unroll
            for (int nf = 0; nf < 8; nf++) {
                uint32_t b0 = Kb[(nf * 8 + g) * KLD + kf * 8 + t];
                uint32_t b1 = Kb[(nf * 8 + g) * KLD + kf * 8 + t + 4];
                mma8(s[0][nf], qf[0][kf], b0, b1);
                mma8(s[1][nf], qf[1][kf], b0, b1);
            }
        }

        // online softmax per m-fragment
#pragma unroll
        for (int mf = 0; mf < 2; mf++) {
            float tmax0 = -1e30f, tmax1 = -1e30f;
#pragma unroll
            for (int nf = 0; nf < 8; nf++) {
                tmax0 = fmaxf(tmax0, fmaxf(s[mf][nf][0], s[mf][nf][1]));
                tmax1 = fmaxf(tmax1, fmaxf(s[mf][nf][2], s[mf][nf][3]));
            }
            tmax0 = fmaxf(tmax0, __shfl_xor_sync(0xffffffffu, tmax0, 1));
            tmax0 = fmaxf(tmax0, __shfl_xor_sync(0xffffffffu, tmax0, 2));
            tmax1 = fmaxf(tmax1, __shfl_xor_sync(0xffffffffu, tmax1, 1));
            tmax1 = fmaxf(tmax1, __shfl_xor_sync(0xffffffffu, tmax1, 2));

            float mn0 = fmaxf(mm[mf][0], tmax0), mn1 = fmaxf(mm[mf][1], tmax1);
            float al0 = __expf(mm[mf][0] - mn0), al1 = __expf(mm[mf][1] - mn1);

            const int prow0 = (mf == 0) ? pr00 : pr10;
            const int prow1 = (mf == 0) ? pr01 : pr11;
            float rs0 = 0.f, rs1 = 0.f;
#pragma unroll
            for (int nf = 0; nf < 8; nf++) {
                uint32_t r0 = rna_bits(__expf(s[mf][nf][0] - mn0));
                uint32_t r1 = rna_bits(__expf(s[mf][nf][1] - mn0));
                uint32_t r2 = rna_bits(__expf(s[mf][nf][2] - mn1));
                uint32_t r3 = rna_bits(__expf(s[mf][nf][3] - mn1));
                rs0 += __uint_as_float(r0) + __uint_as_float(r1);
                rs1 += __uint_as_float(r2) + __uint_as_float(r3);
                Pu[prow0 + nf * 8 + 2 * t]     = r0;
                Pu[prow0 + nf * 8 + 2 * t + 1] = r1;
                Pu[prow1 + nf * 8 + 2 * t]     = r2;
                Pu[prow1 + nf * 8 + 2 * t + 1] = r3;
            }
            rs0 += __shfl_xor_sync(0xffffffffu, rs0, 1);
            rs0 += __shfl_xor_sync(0xffffffffu, rs0, 2);
            rs1 += __shfl_xor_sync(0xffffffffu, rs1, 1);
            rs1 += __shfl_xor_sync(0xffffffffu, rs1, 2);
            ll[mf][0] = ll[mf][0] * al0 + rs0;
            ll[mf][1] = ll[mf][1] * al1 + rs1;
            mm[mf][0] = mn0; mm[mf][1] = mn1;
#pragma unroll
            for (int nf = 0; nf < 8; nf++) {
                o[mf][nf][0] *= al0; o[mf][nf][1] *= al0;
                o[mf][nf][2] *= al1; o[mf][nf][3] *= al1;
            }
        }
        __syncwarp();

        // O += P * V
        const uint32_t* Pr = (const uint32_t*)Ps;
#pragma unroll
        for (int kf = 0; kf < 8; kf++) {
            uint32_t a0[4], a1[4];
            a0[0] = Pr[pr00 + kf * 8 + t];     a0[1] = Pr[pr01 + kf * 8 + t];
            a0[2] = Pr[pr00 + kf * 8 + t + 4]; a0[3] = Pr[pr01 + kf * 8 + t + 4];
            a1[0] = Pr[pr10 + kf * 8 + t];     a1[1] = Pr[pr11 + kf * 8 + t];
            a1[2] = Pr[pr10 + kf * 8 + t + 4]; a1[3] = Pr[pr11 + kf * 8 + t + 4];
#pragma unroll
            for (int nf = 0; nf < 8; nf++) {
                uint32_t b0 = Vb[(kf * 8 + t) * VLD + nf * 8 + g];
                uint32_t b1 = Vb[(kf * 8 + t + 4) * VLD + nf * 8 + g];
                mma8(o[0][nf], a0, b0, b1);
                mma8(o[1][nf], a1, b0, b1);
            }
        }
        __syncthreads();
    }

#pragma unroll
    for (int mf = 0; mf < 2; mf++) {
        float inv0 = 1.f / ll[mf][0], inv1 = 1.f / ll[mf][1];
        int row = q0 + w * 32 + mf * 16 + g;
        float* Orow = O + (size_t)(b * Ssz + row) * 2048 + z * 1024 + h * 64;
#pragma unroll
        for (int nf = 0; nf < 8; nf++) {
            int col = nf * 8 + 2 * t;
            float2 lo = { rna_tf32(o[mf][nf][0] * inv0), rna_tf32(o[mf][nf][1] * inv0) };
            float2 hi = { rna_tf32(o[mf][nf][2] * inv1), rna_tf32(o[mf][nf][3] * inv1) };
            *(float2*)(Orow + col) = lo;
            *(float2*)(Orow + 8 * 2048 + col) = hi;
        }
    }
}

// ---------------------------------------------------------------------------
// pack kernels: round weights to tf32 and interleave into wide B matrices
// ---------------------------------------------------------------------------
__device__ __forceinline__ float4 rna4(float4 v) {
    v.x = rna_tf32(v.x); v.y = rna_tf32(v.y);
    v.z = rna_tf32(v.z); v.w = rna_tf32(v.w);
    return v;
}

__global__ void pack_qkv(const float4* w0, const float4* w1, const float4* w2,
                         const float4* w3, const float4* w4, const float4* w5,
                         const float4* b0, const float4* b1, const float4* b2,
                         const float4* b3, const float4* b4, const float4* b5,
                         float4* out, float4* bout)
{
    const float4* ws[6] = { w0, w1, w2, w3, w4, w5 };
    const float4* bs[6] = { b0, b1, b2, b3, b4, b5 };
    int i = blockIdx.x * blockDim.x + threadIdx.x;
    int st = gridDim.x * blockDim.x;
    for (; i < 262144; i += st) {
        int k = i >> 8, n4 = i & 255;
#pragma unroll
        for (int j = 0; j < 6; j++)
            out[(size_t)k * 1536 + j * 256 + n4] = rna4(ws[j][i]);
        if (i < 256) {
#pragma unroll
            for (int j = 0; j < 6; j++)
                bout[j * 256 + i] = bs[j][i];
        }
    }
}

__global__ void pack_wo(const float4* w0, const float4* w1,
                        const float4* b0, const float4* b1,
                        float4* out, float4* bout)
{
    int i = blockIdx.x * blockDim.x + threadIdx.x;
    int st = gridDim.x * blockDim.x;
    for (; i < 262144; i += st) {
        int k = i >> 8, n4 = i & 255;
        out[(size_t)k * 512 + n4]       = rna4(w0[i]);
        out[(size_t)k * 512 + 256 + n4] = rna4(w1[i]);
        if (i < 256) { bout[i] = b0[i]; bout[256 + i] = b1[i]; }
    }
}

__global__ void round_tf32_copy(const float4* __restrict__ in, float4* __restrict__ out, int n4)
{
    int i = blockIdx.x * blockDim.x + threadIdx.x;
    int st = gridDim.x * blockDim.x;
    for (; i < n4; i += st) out[i] = rna4(in[i]);
}

// ---------------------------------------------------------------------------
// diff: D[M,1024] = rna(T[:, :1024] - lambda * T[:, 1024:])
// ---------------------------------------------------------------------------
__global__ void diff_lambda(const float4* __restrict__ T, float4* __restrict__ D,
                            const float* __restrict__ lambda_param,
                            const unsigned* __restrict__ layer_idx_bits)
{
    unsigned bits = *layer_idx_bits;
    float lf = (bits < 10000u) ? (float)bits : __uint_as_float(bits);
    float e = __expf(-0.3f * fmaxf(lf - 1.0f, 0.0f));
    float lam = fminf(fmaxf((0.8f - 0.6f * e) * lambda_param[0], 0.1f), 0.9f);

    int i = blockIdx.x * blockDim.x + threadIdx.x;
    int st = gridDim.x * blockDim.x;
    const int n4 = Msz * 1024 / 4;
    for (; i < n4; i += st) {
        int r = i >> 8, c4 = i & 255;
        float4 a = T[(size_t)r * 512 + c4];
        float4 b = T[(size_t)r * 512 + 256 + c4];
        float4 v;
        v.x = rna_tf32(fmaf(-lam, b.x, a.x));
        v.y = rna_tf32(fmaf(-lam, b.y, a.y));
        v.z = rna_tf32(fmaf(-lam, b.z, a.z));
        v.w = rna_tf32(fmaf(-lam, b.w, a.w));
        D[i] = v;
    }
}

// ---------------------------------------------------------------------------
extern "C" void kernel_launch(void* const* d_in, const int* in_sizes, int n_in,
                              void* d_out, int out_size)
{
    const float*    x            = (const float*)d_in[0];
    const unsigned* layer_idx    = (const unsigned*)d_in[1];
    const float*    lambda_param = (const float*)d_in[2];

    const float *Wq1, *bq1, *Wk1, *bk1, *Wv1, *bv1, *Wo1, *bo1;
    const float *Wq2, *bq2, *Wk2, *bk2, *Wv2, *bv2, *Wo2, *bo2;

    bool sig_order = (in_sizes[4] < 100000);
    if (!sig_order) {
        Wq1 = (const float*)d_in[3];  Wk1 = (const float*)d_in[4];
        Wv1 = (const float*)d_in[5];  Wo1 = (const float*)d_in[6];
        bq1 = (const float*)d_in[7];  bk1 = (const float*)d_in[8];
        bv1 = (const float*)d_in[9];  bo1 = (const float*)d_in[10];
        Wq2 = (const float*)d_in[11]; Wk2 = (const float*)d_in[12];
        Wv2 = (const float*)d_in[13]; Wo2 = (const float*)d_in[14];
        bq2 = (const float*)d_in[15]; bk2 = (const float*)d_in[16];
        bv2 = (const float*)d_in[17]; bo2 = (const float*)d_in[18];
    } else {
        Wq1 = (const float*)d_in[3];  bq1 = (const float*)d_in[4];
        Wk1 = (const float*)d_in[5];  bk1 = (const float*)d_in[6];
        Wv1 = (const float*)d_in[7];  bv1 = (const float*)d_in[8];
        Wo1 = (const float*)d_in[9];  bo1 = (const float*)d_in[10];
        Wq2 = (const float*)d_in[11]; bq2 = (const float*)d_in[12];
        Wk2 = (const float*)d_in[13]; bk2 = (const float*)d_in[14];
        Wv2 = (const float*)d_in[15]; bv2 = (const float*)d_in[16];
        Wo2 = (const float*)d_in[17]; bo2 = (const float*)d_in[18];
    }
    const float* Wp = (const float*)d_in[19];
    const float* bp = (const float*)d_in[20];

    float* s = nullptr;
    cudaGetSymbolAddress((void**)&s, g_scratch);
    float* XR   = s;                          // [4096,1024]
    float* QKV  = s + 1 * CHUNK;              // [4096,6144]
    float* OB   = s + 7 * CHUNK;              // [4096,2048]
    float* TB   = s + 9 * CHUNK;              // [4096,2048]
    float* DB   = s + 11 * CHUNK;             // [4096,1024]
    float* WQKV = s + 12 * CHUNK;             // [1024,6144]
    float* WWO  = s + 12 * CHUNK + 6 * WCH;   // [1024,2048]
    float* WPR  = s + 12 * CHUNK + 8 * WCH;   // [1024,1024]
    float* BQKV = s + 12 * CHUNK + 9 * WCH;   // [6144]
    float* BWO  = BQKV + 8192;                // [2048]

    cudaFuncSetAttribute(gemm_mma<true, false>,  cudaFuncAttributeMaxDynamicSharedMemorySize, GEMM_SMEM);
    cudaFuncSetAttribute(gemm_mma<false, true>,  cudaFuncAttributeMaxDynamicSharedMemorySize, GEMM_SMEM);
    cudaFuncSetAttribute(gemm_mma<false, false>, cudaFuncAttributeMaxDynamicSharedMemorySize, GEMM_SMEM);
    cudaFuncSetAttribute(flash_mma, cudaFuncAttributeMaxDynamicSharedMemorySize, ATT_SMEM);

    // prep: round x; pack + round weights
    round_tf32_copy<<<512, 256>>>((const float4*)x, (float4*)XR, (int)(Msz * 1024ull / 4));
    pack_qkv<<<1024, 256>>>((const float4*)Wq1, (const float4*)Wk1, (const float4*)Wv1,
                            (const float4*)Wq2, (const float4*)Wk2, (const float4*)Wv2,
                            (const float4*)bq1, (const float4*)bk1, (const float4*)bv1,
                            (const float4*)bq2, (const float4*)bk2, (const float4*)bv2,
                            (float4*)WQKV, (float4*)BQKV);
    pack_wo<<<1024, 256>>>((const float4*)Wo1, (const float4*)Wo2,
                           (const float4*)bo1, (const float4*)bo2,
                           (float4*)WWO, (float4*)BWO);
    round_tf32_copy<<<256, 256>>>((const float4*)Wp, (float4*)WPR, (int)(WCH / 4));

    // fused QKV projection: [4096,1024] x [1024,6144]
    gemm_mma<true, false><<<dim3(24, 32), 256, GEMM_SMEM>>>(XR, WQKV, BQKV, QKV, 6144, 1024);

    // attention, both branches
    flash_mma<<<dim3(Ssz / 256, Bsz * Hsz, 2), 256, ATT_SMEM>>>(QKV, OB);

    // fused output projections (block-diagonal A)
    gemm_mma<false, true><<<dim3(8, 32), 256, GEMM_SMEM>>>(OB, WWO, BWO, TB, 2048, 2048);

    // diff + compact + round
    diff_lambda<<<512, 256>>>((const float4*)TB, (float4*)DB, lambda_param, layer_idx);

    // final projection into d_out
    gemm_mma<false, false><<<dim3(4, 32), 256, GEMM_SMEM>>>(DB, WPR, bp, (float*)d_out, 1024, 1024);
}